// round 14
// baseline (speedup 1.0000x reference)
#include <cuda_runtime.h>
#include <cuda_fp16.h>
#include <cstdint>

static __device__ __forceinline__ float ex2f(float x){
    float r; asm("ex2.approx.f32 %0, %1;" : "=f"(r) : "f"(x)); return r;
}
static __device__ __forceinline__ float rcpf(float x){
    float r; asm("rcp.approx.f32 %0, %1;" : "=f"(r) : "f"(x)); return r;
}
#define L2E 1.4426950408889634f
static __device__ __forceinline__ float sigmoid_acc(float x){
    return rcpf(1.0f + ex2f(-x * L2E));
}
static __device__ __forceinline__ float tanh_acc(float x){
    return 1.0f - 2.0f * rcpf(ex2f(2.0f * L2E * x) + 1.0f);
}

#define TT 8192
#define HH 128
#define II 16
#define PP 1024
#define NKK 9        // K = 144 = 128 (h) + 16 (x)

// Per-(batch, photo) h-vector accumulators (linearity: FC applied once at end).
__device__ float g_sums[32][PP][HH];
__device__ float g_cnt[32][PP];

// m16n8k16 fp16 MMA, fp32 accumulate.
static __device__ __forceinline__ void mma16816(
    float& d0, float& d1, float& d2, float& d3,
    uint32_t a0, uint32_t a1, uint32_t a2, uint32_t a3,
    uint32_t b0, uint32_t b1)
{
    asm("mma.sync.aligned.m16n8k16.row.col.f32.f16.f16.f32 "
        "{%0,%1,%2,%3}, {%4,%5,%6,%7}, {%8,%9}, {%0,%1,%2,%3};"
        : "+f"(d0), "+f"(d1), "+f"(d2), "+f"(d3)
        : "r"(a0), "r"(a1), "r"(a2), "r"(a3), "r"(b0), "r"(b1));
}

static __device__ __forceinline__ uint32_t pack_w(
    const float* __restrict__ Whh, const float* __restrict__ Wih, int r, int k)
{
    float2 f;
    if (k < HH) f = *reinterpret_cast<const float2*>(Whh + (size_t)r * HH + k);
    else        f = *reinterpret_cast<const float2*>(Wih + (size_t)r * II + (k - HH));
    __half2 h = __floats2half2_rn(f.x, f.y);
    return *reinterpret_cast<uint32_t*>(&h);
}

// vB layout (72 u32), validated in R7.
static __device__ __forceinline__ int vb_idx(int j){
    int kk = j >> 3, rem = j & 7;
    return (rem < 4) ? ((4*kk + rem)*2) : ((4*kk + rem - 4)*2 + 1);
}

__global__ void __launch_bounds__(256) zero_scratch_kernel(){
    size_t idx = (size_t)blockIdx.x * 256 + threadIdx.x;
    if (idx < (size_t)32 * PP * HH / 4)
        reinterpret_cast<float4*>(g_sums)[idx] = make_float4(0.f, 0.f, 0.f, 0.f);
}

// R13 skeleton (proven 5269us) with two changes:
//  1. ld+add+st segment accumulate -> single RED.GLOBAL.ADD (atomicAdd, no
//     return) in S2; the L2 load leaves S1 entirely.
//  2. S2 roles moved to the HIGHEST-wid warps (hi-wid-first arbiter): cell
//     update on warps 12-15, x-part on 11, x prefetch on 10, count on 9.
__global__ void __launch_bounds__(512, 1)
lstm_mma8_kernel(const float* __restrict__ x,
                 const float* __restrict__ Wih,
                 const float* __restrict__ Whh,
                 const float* __restrict__ bih,
                 const float* __restrict__ bhh)
{
    __shared__ float xsh[2][II];                       // fp32 x double buffer
    __shared__ float act[512];                         // activated gates
    __shared__ __align__(16) uint32_t vB[72];          // fp16 [h;x] B-operand
    __shared__ float cnt_s[PP];

    const int tid = threadIdx.x;
    const int wid = tid >> 5;
    const int lid = tid & 31;
    const int b   = blockIdx.x;
    const int g   = lid >> 2;
    const int tq  = lid & 3;

    // ---- resident A fragments over [W_hh | W_ih], K=144 (exact R7/R13) ----
    uint32_t aw[2][NKK][4];
    #pragma unroll
    for (int ti = 0; ti < 2; ti++){
        const int r0 = 32*wid + 16*ti + g;
        #pragma unroll
        for (int kk = 0; kk < NKK; kk++){
            const int k0 = 16*kk + 2*tq;
            aw[ti][kk][0] = pack_w(Whh, Wih, r0,     k0);
            aw[ti][kk][1] = pack_w(Whh, Wih, r0 + 8, k0);
            aw[ti][kk][2] = pack_w(Whh, Wih, r0,     k0 + 8);
            aw[ti][kk][3] = pack_w(Whh, Wih, r0 + 8, k0 + 8);
        }
    }
    const float bias = bih[tid] + bhh[tid];
    const bool  is_tanh_gate = ((tid >> 7) == 2);

    // ---- init shared state ----
    const float* xb = x + (size_t)b * TT * II;
    if (tid < 64) vB[tid] = 0u;                        // h(-1) = 0
    if (tid >= 64 && tid < 72){                        // x(0) into vB x-part
        int jj = tid - 64;
        __half2 xp = __floats2half2_rn(xb[2*jj], xb[2*jj + 1]);
        vB[(jj < 4) ? (32 + jj)*2 : (32 + jj - 4)*2 + 1]
            = *reinterpret_cast<uint32_t*>(&xp);
    }
    if (tid < II){ xsh[0][tid] = xb[tid]; xsh[1][tid] = xb[II + tid]; }
    for (int k = tid; k < PP; k += 512) cnt_s[k] = 0.f;
    __syncthreads();

    float c = 0.f;   // cell state: lives in warps 12..15 (slot = tid-384)

    for (int t = 0; t < TT; t++){
        const int p = t & 1;

        // ================= S1: id/prefetch + MMA + act =================
        float* gptr = nullptr;
        if (wid >= 12){                                // my slot's accumulator addr
            const int id = (int)xsh[p][2];
            if ((unsigned)id < (unsigned)PP) gptr = &g_sums[b][id][tid - 384];
        }
        int id9 = -1;
        if (wid == 9 && lid == 0) id9 = (int)xsh[p][2];   // count keeper
        float xr = 0.f;
        if (wid == 10 && lid < 16){                    // prefetch x(t+2)
            int tn = t + 2; if (tn > TT - 1) tn = TT - 1;
            xr = __ldg(xb + (size_t)tn * II + lid);
        }

        float d0=0.f,d1=0.f,d2=0.f,d3=0.f,d4=0.f,d5=0.f,d6=0.f,d7=0.f;
        #pragma unroll
        for (int kk = 0; kk < NKK; kk++){
            const uint2 bb = *reinterpret_cast<const uint2*>(&vB[(4*kk + tq)*2]);
            mma16816(d0,d1,d2,d3, aw[0][kk][0],aw[0][kk][1],aw[0][kk][2],aw[0][kk][3], bb.x, bb.y);
            mma16816(d4,d5,d6,d7, aw[1][kk][0],aw[1][kk][1],aw[1][kk][2],aw[1][kk][3], bb.x, bb.y);
        }
        const int sl = (lid & 7) * 4;
        const float v0 = __shfl_sync(0xffffffffu, d0, sl);
        const float v1 = __shfl_sync(0xffffffffu, d2, sl);
        const float v2 = __shfl_sync(0xffffffffu, d4, sl);
        const float v3 = __shfl_sync(0xffffffffu, d6, sl);
        const int sel = lid >> 3;
        const float gpre = ((sel == 0) ? v0 : (sel == 1) ? v1 : (sel == 2) ? v2 : v3) + bias;
        act[tid] = is_tanh_gate ? tanh_acc(gpre) : sigmoid_acc(gpre);
        __syncthreads();   // A

        // ===== S2 (high-priority warps): cell + vB + RED accumulate =====
        if (wid >= 12){
            const int slot = tid - 384;                // 0..127
            const float iv = act[slot];
            const float fv = act[HH + slot];
            const float gv = act[2*HH + slot];
            const float ov = act[3*HH + slot];
            c = fv * c + iv * gv;
            const float hn = ov * tanh_acc(c);
            const float hn1 = __shfl_down_sync(0xffffffffu, hn, 1);
            if (!(slot & 1)){
                __half2 hp = __floats2half2_rn(hn, hn1);
                vB[vb_idx(slot >> 1)] = *reinterpret_cast<uint32_t*>(&hp);
            }
            if (gptr) atomicAdd(gptr, hn);             // RED.GLOBAL.ADD (no return)
        } else if (wid == 11 && lid < 8){              // x(t+1) -> vB x-part
            const float* xsrc = xsh[(t + 1) & 1];
            __half2 xp = __floats2half2_rn(xsrc[2*lid], xsrc[2*lid + 1]);
            vB[(lid < 4) ? (32 + lid)*2 : (32 + lid - 4)*2 + 1]
                = *reinterpret_cast<uint32_t*>(&xp);
        } else if (wid == 10 && lid < 16){             // x(t+2) over retired x(t)
            xsh[p][lid] = xr;
        } else if (wid == 9 && lid == 0){
            if ((unsigned)id9 < (unsigned)PP) cnt_s[id9] += 1.f;
        }
        __syncthreads();   // B
    }

    // ---- export counts ----
    for (int k = tid; k < PP; k += 512) g_cnt[b][k] = cnt_s[k];
}

// Final pass: out[b][id][ch] = cnt ? Wfc[ch].sums_h[b][id]/cnt + bfc[ch] : 0
__global__ void __launch_bounds__(128) fc_epilogue_kernel(
    const float* __restrict__ Wfc, const float* __restrict__ bfc,
    float* __restrict__ out)
{
    __shared__ float wsh[3][HH];
    const int tid = threadIdx.x;
    const int wid = tid >> 5;
    const int lid = tid & 31;
    const int b     = blockIdx.x;
    const int chunk = blockIdx.y;     // 8 chunks of 128 ids

    wsh[0][tid] = Wfc[tid];
    wsh[1][tid] = Wfc[HH + tid];
    wsh[2][tid] = Wfc[2*HH + tid];
    __syncthreads();

    const float b0 = bfc[0], b1 = bfc[1], b2 = bfc[2];
    for (int i = 0; i < 32; i++){
        const int id = chunk*128 + wid*32 + i;
        const float4 s = *reinterpret_cast<const float4*>(&g_sums[b][id][lid*4]);
        float p0 = s.x*wsh[0][4*lid] + s.y*wsh[0][4*lid+1] + s.z*wsh[0][4*lid+2] + s.w*wsh[0][4*lid+3];
        float p1 = s.x*wsh[1][4*lid] + s.y*wsh[1][4*lid+1] + s.z*wsh[1][4*lid+2] + s.w*wsh[1][4*lid+3];
        float p2 = s.x*wsh[2][4*lid] + s.y*wsh[2][4*lid+1] + s.z*wsh[2][4*lid+2] + s.w*wsh[2][4*lid+3];
        #pragma unroll
        for (int m = 16; m >= 1; m >>= 1){
            p0 += __shfl_xor_sync(0xffffffffu, p0, m);
            p1 += __shfl_xor_sync(0xffffffffu, p1, m);
            p2 += __shfl_xor_sync(0xffffffffu, p2, m);
        }
        if (lid == 0){
            const float cn = g_cnt[b][id];
            float* o = out + ((size_t)b * PP + id) * 3;
            if (cn == 0.f){ o[0] = 0.f; o[1] = 0.f; o[2] = 0.f; }
            else {
                const float r = rcpf(cn);
                o[0] = p0 * r + b0; o[1] = p1 * r + b1; o[2] = p2 * r + b2;
            }
        }
    }
}

extern "C" void kernel_launch(void* const* d_in, const int* in_sizes, int n_in,
                              void* d_out, int out_size)
{
    const float *x = 0, *Wih = 0, *Whh = 0, *b1 = 0, *b2 = 0, *Wfc = 0, *bfc = 0;
    for (int i = 0; i < n_in; i++){
        const float* p = (const float*)d_in[i];
        switch (in_sizes[i]){
            case 32*8192*16: x   = p; break;
            case 512*16:     Wih = p; break;
            case 512*128:    Whh = p; break;
            case 512:        if (!b1) b1 = p; else b2 = p; break;
            case 3*128:      Wfc = p; break;
            case 3:          bfc = p; break;
            default: break;
        }
    }
    if (!x)   x   = (const float*)d_in[0];
    if (!Wih) Wih = (const float*)d_in[1];
    if (!Whh) Whh = (const float*)d_in[2];
    if (!b1)  b1  = (const float*)d_in[3];
    if (!b2)  b2  = (const float*)d_in[4];
    if (!Wfc) Wfc = (const float*)d_in[5];
    if (!bfc) bfc = (const float*)d_in[6];

    float* out = (float*)d_out;

    zero_scratch_kernel<<<(32*PP*HH/4 + 255)/256, 256>>>();
    lstm_mma8_kernel<<<32, 512>>>(x, Wih, Whh, b1, b2);
    fc_epilogue_kernel<<<dim3(32, 8), 128>>>(Wfc, bfc, out);
}

// round 16
// speedup vs baseline: 1.0850x; 1.0850x over previous
#include <cuda_runtime.h>
#include <cuda_fp16.h>
#include <cstdint>

static __device__ __forceinline__ float ex2f(float x){
    float r; asm("ex2.approx.f32 %0, %1;" : "=f"(r) : "f"(x)); return r;
}
static __device__ __forceinline__ float rcpf(float x){
    float r; asm("rcp.approx.f32 %0, %1;" : "=f"(r) : "f"(x)); return r;
}
#define L2E 1.4426950408889634f
static __device__ __forceinline__ float sigmoid_acc(float x){
    return rcpf(1.0f + ex2f(-x * L2E));
}
static __device__ __forceinline__ float tanh_acc(float x){
    return 1.0f - 2.0f * rcpf(ex2f(2.0f * L2E * x) + 1.0f);
}

#define TT 8192
#define HH 128
#define II 16
#define PP 1024
#define NKK 9        // K = 144 = 128 (h) + 16 (x)

// Per-(batch, photo) h-vector accumulators (linearity: FC applied once at end).
__device__ float g_sums[32][PP][HH];
__device__ float g_cnt[32][PP];

// m16n8k16 fp16 MMA, fp32 accumulate.
static __device__ __forceinline__ void mma16816(
    float& d0, float& d1, float& d2, float& d3,
    uint32_t a0, uint32_t a1, uint32_t a2, uint32_t a3,
    uint32_t b0, uint32_t b1)
{
    asm("mma.sync.aligned.m16n8k16.row.col.f32.f16.f16.f32 "
        "{%0,%1,%2,%3}, {%4,%5,%6,%7}, {%8,%9}, {%0,%1,%2,%3};"
        : "+f"(d0), "+f"(d1), "+f"(d2), "+f"(d3)
        : "r"(a0), "r"(a1), "r"(a2), "r"(a3), "r"(b0), "r"(b1));
}

static __device__ __forceinline__ uint32_t pack_w(
    const float* __restrict__ Whh, const float* __restrict__ Wih, int r, int k)
{
    float2 f;
    if (k < HH) f = *reinterpret_cast<const float2*>(Whh + (size_t)r * HH + k);
    else        f = *reinterpret_cast<const float2*>(Wih + (size_t)r * II + (k - HH));
    __half2 h = __floats2half2_rn(f.x, f.y);
    return *reinterpret_cast<uint32_t*>(&h);
}

// vB layout (72 u32), validated in R7.
static __device__ __forceinline__ int vb_idx(int j){
    int kk = j >> 3, rem = j & 7;
    return (rem < 4) ? ((4*kk + rem)*2) : ((4*kk + rem - 4)*2 + 1);
}

__global__ void __launch_bounds__(256) zero_scratch_kernel(){
    size_t idx = (size_t)blockIdx.x * 256 + threadIdx.x;
    if (idx < (size_t)32 * PP * HH / 4)
        reinterpret_cast<float4*>(g_sums)[idx] = make_float4(0.f, 0.f, 0.f, 0.f);
}

// EXACT R13 structure (proven 5269us) with ONE change: the ldcg(S1)+add+
// stcg(S2) segment accumulate becomes a single no-return atomicAdd in S2.
// CRITICAL (R15 lesson): the photo id is read in S1, BEFORE barrier A —
// in S2 warp 5 overwrites xsh[p] with x(t+2), so an S2 read races.
__global__ void __launch_bounds__(512, 1)
lstm_mma10_kernel(const float* __restrict__ x,
                  const float* __restrict__ Wih,
                  const float* __restrict__ Whh,
                  const float* __restrict__ bih,
                  const float* __restrict__ bhh)
{
    __shared__ float xsh[2][II];                       // fp32 x double buffer
    __shared__ float act[512];                         // activated gates
    __shared__ __align__(16) uint32_t vB[72];          // fp16 [h;x] B-operand
    __shared__ float cnt_s[PP];

    const int tid = threadIdx.x;
    const int wid = tid >> 5;
    const int lid = tid & 31;
    const int b   = blockIdx.x;
    const int g   = lid >> 2;
    const int tq  = lid & 3;

    // ---- resident A fragments over [W_hh | W_ih], K=144 ----
    uint32_t aw[2][NKK][4];
    #pragma unroll
    for (int ti = 0; ti < 2; ti++){
        const int r0 = 32*wid + 16*ti + g;
        #pragma unroll
        for (int kk = 0; kk < NKK; kk++){
            const int k0 = 16*kk + 2*tq;
            aw[ti][kk][0] = pack_w(Whh, Wih, r0,     k0);
            aw[ti][kk][1] = pack_w(Whh, Wih, r0 + 8, k0);
            aw[ti][kk][2] = pack_w(Whh, Wih, r0,     k0 + 8);
            aw[ti][kk][3] = pack_w(Whh, Wih, r0 + 8, k0 + 8);
        }
    }
    const float bias = bih[tid] + bhh[tid];
    const bool  is_tanh_gate = ((tid >> 7) == 2);

    // ---- init shared state ----
    const float* xb = x + (size_t)b * TT * II;
    if (tid < 64) vB[tid] = 0u;                        // h(-1) = 0
    if (tid >= 64 && tid < 72){                        // x(0) into vB x-part
        int jj = tid - 64;
        __half2 xp = __floats2half2_rn(xb[2*jj], xb[2*jj + 1]);
        vB[(jj < 4) ? (32 + jj)*2 : (32 + jj - 4)*2 + 1]
            = *reinterpret_cast<uint32_t*>(&xp);
    }
    if (tid < II){ xsh[0][tid] = xb[tid]; xsh[1][tid] = xb[II + tid]; }
    for (int k = tid; k < PP; k += 512) cnt_s[k] = 0.f;
    __syncthreads();

    float c = 0.f;   // cell state (threads 0..127)

    for (int t = 0; t < TT; t++){
        const int p = t & 1;

        // ========== S1: id reads (safe window) + prefetch + MMA + act ==========
        int idq = -1;
        if (tid < HH) idq = (int)xsh[p][2];            // id(t) for my accumulate
        int id6 = -1;
        if (wid == 6 && lid == 0) id6 = (int)xsh[p][2];   // count keeper
        float xr = 0.f;
        if (wid == 5 && lid < 16){                     // prefetch x(t+2)
            int tn = t + 2; if (tn > TT - 1) tn = TT - 1;
            xr = __ldg(xb + (size_t)tn * II + lid);
        }

        float d0=0.f,d1=0.f,d2=0.f,d3=0.f,d4=0.f,d5=0.f,d6=0.f,d7=0.f;
        #pragma unroll
        for (int kk = 0; kk < NKK; kk++){
            const uint2 bb = *reinterpret_cast<const uint2*>(&vB[(4*kk + tq)*2]);
            mma16816(d0,d1,d2,d3, aw[0][kk][0],aw[0][kk][1],aw[0][kk][2],aw[0][kk][3], bb.x, bb.y);
            mma16816(d4,d5,d6,d7, aw[1][kk][0],aw[1][kk][1],aw[1][kk][2],aw[1][kk][3], bb.x, bb.y);
        }
        const int sl = (lid & 7) * 4;
        const float v0 = __shfl_sync(0xffffffffu, d0, sl);
        const float v1 = __shfl_sync(0xffffffffu, d2, sl);
        const float v2 = __shfl_sync(0xffffffffu, d4, sl);
        const float v3 = __shfl_sync(0xffffffffu, d6, sl);
        const int sel = lid >> 3;
        const float gpre = ((sel == 0) ? v0 : (sel == 1) ? v1 : (sel == 2) ? v2 : v3) + bias;
        act[tid] = is_tanh_gate ? tanh_acc(gpre) : sigmoid_acc(gpre);
        __syncthreads();   // A

        // ==== S2: cell update + vB refresh + RED accumulate + misc ====
        if (tid < HH){
            const float iv = act[tid];
            const float fv = act[HH + tid];
            const float gv = act[2*HH + tid];
            const float ov = act[3*HH + tid];
            c = fv * c + iv * gv;
            const float hn = ov * tanh_acc(c);
            const float hn1 = __shfl_down_sync(0xffffffffu, hn, 1);
            if (!(tid & 1)){
                __half2 hp = __floats2half2_rn(hn, hn1);
                vB[vb_idx(tid >> 1)] = *reinterpret_cast<uint32_t*>(&hp);
            }
            if ((unsigned)idq < (unsigned)PP)
                atomicAdd(&g_sums[b][idq][tid], hn);   // RED.GLOBAL.ADD, no return
        } else if (tid < 136){                         // warp 4: x(t+1) -> vB x-part
            const int jj = tid - 128;
            const float* xsrc = xsh[(t + 1) & 1];
            __half2 xp = __floats2half2_rn(xsrc[2*jj], xsrc[2*jj + 1]);
            vB[(jj < 4) ? (32 + jj)*2 : (32 + jj - 4)*2 + 1]
                = *reinterpret_cast<uint32_t*>(&xp);
        } else if (wid == 5 && lid < 16){              // x(t+2) over retired x(t)
            xsh[p][lid] = xr;
        } else if (wid == 6 && lid == 0){
            if ((unsigned)id6 < (unsigned)PP) cnt_s[id6] += 1.f;
        }
        __syncthreads();   // B
    }

    // ---- export counts ----
    for (int k = tid; k < PP; k += 512) g_cnt[b][k] = cnt_s[k];
}

// Final pass: out[b][id][ch] = cnt ? Wfc[ch].sums_h[b][id]/cnt + bfc[ch] : 0
__global__ void __launch_bounds__(128) fc_epilogue_kernel(
    const float* __restrict__ Wfc, const float* __restrict__ bfc,
    float* __restrict__ out)
{
    __shared__ float wsh[3][HH];
    const int tid = threadIdx.x;
    const int wid = tid >> 5;
    const int lid = tid & 31;
    const int b     = blockIdx.x;
    const int chunk = blockIdx.y;     // 8 chunks of 128 ids

    wsh[0][tid] = Wfc[tid];
    wsh[1][tid] = Wfc[HH + tid];
    wsh[2][tid] = Wfc[2*HH + tid];
    __syncthreads();

    const float b0 = bfc[0], b1 = bfc[1], b2 = bfc[2];
    for (int i = 0; i < 32; i++){
        const int id = chunk*128 + wid*32 + i;
        const float4 s = *reinterpret_cast<const float4*>(&g_sums[b][id][lid*4]);
        float p0 = s.x*wsh[0][4*lid] + s.y*wsh[0][4*lid+1] + s.z*wsh[0][4*lid+2] + s.w*wsh[0][4*lid+3];
        float p1 = s.x*wsh[1][4*lid] + s.y*wsh[1][4*lid+1] + s.z*wsh[1][4*lid+2] + s.w*wsh[1][4*lid+3];
        float p2 = s.x*wsh[2][4*lid] + s.y*wsh[2][4*lid+1] + s.z*wsh[2][4*lid+2] + s.w*wsh[2][4*lid+3];
        #pragma unroll
        for (int m = 16; m >= 1; m >>= 1){
            p0 += __shfl_xor_sync(0xffffffffu, p0, m);
            p1 += __shfl_xor_sync(0xffffffffu, p1, m);
            p2 += __shfl_xor_sync(0xffffffffu, p2, m);
        }
        if (lid == 0){
            const float cn = g_cnt[b][id];
            float* o = out + ((size_t)b * PP + id) * 3;
            if (cn == 0.f){ o[0] = 0.f; o[1] = 0.f; o[2] = 0.f; }
            else {
                const float r = rcpf(cn);
                o[0] = p0 * r + b0; o[1] = p1 * r + b1; o[2] = p2 * r + b2;
            }
        }
    }
}

extern "C" void kernel_launch(void* const* d_in, const int* in_sizes, int n_in,
                              void* d_out, int out_size)
{
    const float *x = 0, *Wih = 0, *Whh = 0, *b1 = 0, *b2 = 0, *Wfc = 0, *bfc = 0;
    for (int i = 0; i < n_in; i++){
        const float* p = (const float*)d_in[i];
        switch (in_sizes[i]){
            case 32*8192*16: x   = p; break;
            case 512*16:     Wih = p; break;
            case 512*128:    Whh = p; break;
            case 512:        if (!b1) b1 = p; else b2 = p; break;
            case 3*128:      Wfc = p; break;
            case 3:          bfc = p; break;
            default: break;
        }
    }
    if (!x)   x   = (const float*)d_in[0];
    if (!Wih) Wih = (const float*)d_in[1];
    if (!Whh) Whh = (const float*)d_in[2];
    if (!b1)  b1  = (const float*)d_in[3];
    if (!b2)  b2  = (const float*)d_in[4];
    if (!Wfc) Wfc = (const float*)d_in[5];
    if (!bfc) bfc = (const float*)d_in[6];

    float* out = (float*)d_out;

    zero_scratch_kernel<<<(32*PP*HH/4 + 255)/256, 256>>>();
    lstm_mma10_kernel<<<32, 512>>>(x, Wih, Whh, b1, b2);
    fc_epilogue_kernel<<<dim3(32, 8), 128>>>(Wfc, bfc, out);
}

// round 17
// speedup vs baseline: 1.1021x; 1.0158x over previous
#include <cuda_runtime.h>
#include <cuda_fp16.h>
#include <cstdint>

static __device__ __forceinline__ float ex2f(float x){
    float r; asm("ex2.approx.f32 %0, %1;" : "=f"(r) : "f"(x)); return r;
}
static __device__ __forceinline__ float rcpf(float x){
    float r; asm("rcp.approx.f32 %0, %1;" : "=f"(r) : "f"(x)); return r;
}
#define L2E 1.4426950408889634f
static __device__ __forceinline__ float sigmoid_acc(float x){
    return rcpf(1.0f + ex2f(-x * L2E));
}
static __device__ __forceinline__ float tanh_acc(float x){
    return 1.0f - 2.0f * rcpf(ex2f(2.0f * L2E * x) + 1.0f);
}

#define TT 8192
#define HH 128
#define II 16
#define PP 1024
#define NKK 9        // K = 144 = 128 (h) + 16 (x)

// Per-(batch, photo) h-vector accumulators (linearity: FC applied once at end).
__device__ float g_sums[32][PP][HH];
__device__ float g_cnt[32][PP];

// m16n8k16 fp16 MMA, fp32 accumulate.
static __device__ __forceinline__ void mma16816(
    float& d0, float& d1, float& d2, float& d3,
    uint32_t a0, uint32_t a1, uint32_t a2, uint32_t a3,
    uint32_t b0, uint32_t b1)
{
    asm("mma.sync.aligned.m16n8k16.row.col.f32.f16.f16.f32 "
        "{%0,%1,%2,%3}, {%4,%5,%6,%7}, {%8,%9}, {%0,%1,%2,%3};"
        : "+f"(d0), "+f"(d1), "+f"(d2), "+f"(d3)
        : "r"(a0), "r"(a1), "r"(a2), "r"(a3), "r"(b0), "r"(b1));
}

static __device__ __forceinline__ uint32_t pack_w(
    const float* __restrict__ Whh, const float* __restrict__ Wih, int r, int k)
{
    float2 f;
    if (k < HH) f = *reinterpret_cast<const float2*>(Whh + (size_t)r * HH + k);
    else        f = *reinterpret_cast<const float2*>(Wih + (size_t)r * II + (k - HH));
    __half2 h = __floats2half2_rn(f.x, f.y);
    return *reinterpret_cast<uint32_t*>(&h);
}

// vB layout (72 u32), validated in R7: k-iter kk, quad tq reads uint2 at
// (4kk+tq)*2. Writer of h-pair j:
static __device__ __forceinline__ int vb_idx(int j){
    int kk = j >> 3, rem = j & 7;
    return (rem < 4) ? ((4*kk + rem)*2) : ((4*kk + rem - 4)*2 + 1);
}

__global__ void __launch_bounds__(256) zero_scratch_kernel(){
    size_t idx = (size_t)blockIdx.x * 256 + threadIdx.x;
    if (idx < (size_t)32 * PP * HH / 4)
        reinterpret_cast<float4*>(g_sums)[idx] = make_float4(0.f, 0.f, 0.f, 0.f);
}

// EXACT R16 structure (proven 5108us) with ONE change: the vB h-refresh
// drops the shfl_down+half2-pack+predicated-STS32 in favor of every thread
// converting and storing ITS OWN half via st.shared.b16 — deleting a 26-cyc
// cross-lane dependency from the S2 critical chain.
__global__ void __launch_bounds__(512, 1)
lstm_mma11_kernel(const float* __restrict__ x,
                  const float* __restrict__ Wih,
                  const float* __restrict__ Whh,
                  const float* __restrict__ bih,
                  const float* __restrict__ bhh)
{
    __shared__ float xsh[2][II];                       // fp32 x double buffer
    __shared__ float act[512];                         // activated gates
    __shared__ __align__(16) uint32_t vB[72];          // fp16 [h;x] B-operand
    __shared__ float cnt_s[PP];

    const int tid = threadIdx.x;
    const int wid = tid >> 5;
    const int lid = tid & 31;
    const int b   = blockIdx.x;
    const int g   = lid >> 2;
    const int tq  = lid & 3;

    // ---- resident A fragments over [W_hh | W_ih], K=144 ----
    uint32_t aw[2][NKK][4];
    #pragma unroll
    for (int ti = 0; ti < 2; ti++){
        const int r0 = 32*wid + 16*ti + g;
        #pragma unroll
        for (int kk = 0; kk < NKK; kk++){
            const int k0 = 16*kk + 2*tq;
            aw[ti][kk][0] = pack_w(Whh, Wih, r0,     k0);
            aw[ti][kk][1] = pack_w(Whh, Wih, r0 + 8, k0);
            aw[ti][kk][2] = pack_w(Whh, Wih, r0,     k0 + 8);
            aw[ti][kk][3] = pack_w(Whh, Wih, r0 + 8, k0 + 8);
        }
    }
    const float bias = bih[tid] + bhh[tid];
    const bool  is_tanh_gate = ((tid >> 7) == 2);

    // my vB half-slot address (precomputed once): pair j = tid>>1
    __half* const my_vb_half = reinterpret_cast<__half*>(vB)
                             + (vb_idx(tid >> 1) * 2 + (tid & 1));

    // ---- init shared state ----
    const float* xb = x + (size_t)b * TT * II;
    if (tid < 64) vB[tid] = 0u;                        // h(-1) = 0
    if (tid >= 64 && tid < 72){                        // x(0) into vB x-part
        int jj = tid - 64;
        __half2 xp = __floats2half2_rn(xb[2*jj], xb[2*jj + 1]);
        vB[(jj < 4) ? (32 + jj)*2 : (32 + jj - 4)*2 + 1]
            = *reinterpret_cast<uint32_t*>(&xp);
    }
    if (tid < II){ xsh[0][tid] = xb[tid]; xsh[1][tid] = xb[II + tid]; }
    for (int k = tid; k < PP; k += 512) cnt_s[k] = 0.f;
    __syncthreads();

    float c = 0.f;   // cell state (threads 0..127)

    for (int t = 0; t < TT; t++){
        const int p = t & 1;

        // ========== S1: id reads (safe window) + prefetch + MMA + act ==========
        int idq = -1;
        if (tid < HH) idq = (int)xsh[p][2];            // id(t) for my accumulate
        int id6 = -1;
        if (wid == 6 && lid == 0) id6 = (int)xsh[p][2];   // count keeper
        float xr = 0.f;
        if (wid == 5 && lid < 16){                     // prefetch x(t+2)
            int tn = t + 2; if (tn > TT - 1) tn = TT - 1;
            xr = __ldg(xb + (size_t)tn * II + lid);
        }

        float d0=0.f,d1=0.f,d2=0.f,d3=0.f,d4=0.f,d5=0.f,d6=0.f,d7=0.f;
        #pragma unroll
        for (int kk = 0; kk < NKK; kk++){
            const uint2 bb = *reinterpret_cast<const uint2*>(&vB[(4*kk + tq)*2]);
            mma16816(d0,d1,d2,d3, aw[0][kk][0],aw[0][kk][1],aw[0][kk][2],aw[0][kk][3], bb.x, bb.y);
            mma16816(d4,d5,d6,d7, aw[1][kk][0],aw[1][kk][1],aw[1][kk][2],aw[1][kk][3], bb.x, bb.y);
        }
        const int sl = (lid & 7) * 4;
        const float v0 = __shfl_sync(0xffffffffu, d0, sl);
        const float v1 = __shfl_sync(0xffffffffu, d2, sl);
        const float v2 = __shfl_sync(0xffffffffu, d4, sl);
        const float v3 = __shfl_sync(0xffffffffu, d6, sl);
        const int sel = lid >> 3;
        const float gpre = ((sel == 0) ? v0 : (sel == 1) ? v1 : (sel == 2) ? v2 : v3) + bias;
        act[tid] = is_tanh_gate ? tanh_acc(gpre) : sigmoid_acc(gpre);
        __syncthreads();   // A

        // ==== S2: cell update + direct-b16 vB refresh + RED accumulate ====
        if (tid < HH){
            const float iv = act[tid];
            const float fv = act[HH + tid];
            const float gv = act[2*HH + tid];
            const float ov = act[3*HH + tid];
            c = fv * c + iv * gv;
            const float hn = ov * tanh_acc(c);
            *my_vb_half = __float2half_rn(hn);         // own half, no shfl
            if ((unsigned)idq < (unsigned)PP)
                atomicAdd(&g_sums[b][idq][tid], hn);   // RED.GLOBAL.ADD, no return
        } else if (tid < 136){                         // warp 4: x(t+1) -> vB x-part
            const int jj = tid - 128;
            const float* xsrc = xsh[(t + 1) & 1];
            __half2 xp = __floats2half2_rn(xsrc[2*jj], xsrc[2*jj + 1]);
            vB[(jj < 4) ? (32 + jj)*2 : (32 + jj - 4)*2 + 1]
                = *reinterpret_cast<uint32_t*>(&xp);
        } else if (wid == 5 && lid < 16){              // x(t+2) over retired x(t)
            xsh[p][lid] = xr;
        } else if (wid == 6 && lid == 0){
            if ((unsigned)id6 < (unsigned)PP) cnt_s[id6] += 1.f;
        }
        __syncthreads();   // B
    }

    // ---- export counts ----
    for (int k = tid; k < PP; k += 512) g_cnt[b][k] = cnt_s[k];
}

// Final pass: out[b][id][ch] = cnt ? Wfc[ch].sums_h[b][id]/cnt + bfc[ch] : 0
__global__ void __launch_bounds__(128) fc_epilogue_kernel(
    const float* __restrict__ Wfc, const float* __restrict__ bfc,
    float* __restrict__ out)
{
    __shared__ float wsh[3][HH];
    const int tid = threadIdx.x;
    const int wid = tid >> 5;
    const int lid = tid & 31;
    const int b     = blockIdx.x;
    const int chunk = blockIdx.y;     // 8 chunks of 128 ids

    wsh[0][tid] = Wfc[tid];
    wsh[1][tid] = Wfc[HH + tid];
    wsh[2][tid] = Wfc[2*HH + tid];
    __syncthreads();

    const float b0 = bfc[0], b1 = bfc[1], b2 = bfc[2];
    for (int i = 0; i < 32; i++){
        const int id = chunk*128 + wid*32 + i;
        const float4 s = *reinterpret_cast<const float4*>(&g_sums[b][id][lid*4]);
        float p0 = s.x*wsh[0][4*lid] + s.y*wsh[0][4*lid+1] + s.z*wsh[0][4*lid+2] + s.w*wsh[0][4*lid+3];
        float p1 = s.x*wsh[1][4*lid] + s.y*wsh[1][4*lid+1] + s.z*wsh[1][4*lid+2] + s.w*wsh[1][4*lid+3];
        float p2 = s.x*wsh[2][4*lid] + s.y*wsh[2][4*lid+1] + s.z*wsh[2][4*lid+2] + s.w*wsh[2][4*lid+3];
        #pragma unroll
        for (int m = 16; m >= 1; m >>= 1){
            p0 += __shfl_xor_sync(0xffffffffu, p0, m);
            p1 += __shfl_xor_sync(0xffffffffu, p1, m);
            p2 += __shfl_xor_sync(0xffffffffu, p2, m);
        }
        if (lid == 0){
            const float cn = g_cnt[b][id];
            float* o = out + ((size_t)b * PP + id) * 3;
            if (cn == 0.f){ o[0] = 0.f; o[1] = 0.f; o[2] = 0.f; }
            else {
                const float r = rcpf(cn);
                o[0] = p0 * r + b0; o[1] = p1 * r + b1; o[2] = p2 * r + b2;
            }
        }
    }
}

extern "C" void kernel_launch(void* const* d_in, const int* in_sizes, int n_in,
                              void* d_out, int out_size)
{
    const float *x = 0, *Wih = 0, *Whh = 0, *b1 = 0, *b2 = 0, *Wfc = 0, *bfc = 0;
    for (int i = 0; i < n_in; i++){
        const float* p = (const float*)d_in[i];
        switch (in_sizes[i]){
            case 32*8192*16: x   = p; break;
            case 512*16:     Wih = p; break;
            case 512*128:    Whh = p; break;
            case 512:        if (!b1) b1 = p; else b2 = p; break;
            case 3*128:      Wfc = p; break;
            case 3:          bfc = p; break;
            default: break;
        }
    }
    if (!x)   x   = (const float*)d_in[0];
    if (!Wih) Wih = (const float*)d_in[1];
    if (!Whh) Whh = (const float*)d_in[2];
    if (!b1)  b1  = (const float*)d_in[3];
    if (!b2)  b2  = (const float*)d_in[4];
    if (!Wfc) Wfc = (const float*)d_in[5];
    if (!bfc) bfc = (const float*)d_in[6];

    float* out = (float*)d_out;

    zero_scratch_kernel<<<(32*PP*HH/4 + 255)/256, 256>>>();
    lstm_mma11_kernel<<<32, 512>>>(x, Wih, Whh, b1, b2);
    fc_epilogue_kernel<<<dim3(32, 8), 128>>>(Wfc, bfc, out);
}